// round 11
// baseline (speedup 1.0000x reference)
#include <cuda_runtime.h>

// NCC2D: -mean( cross^2 / (I_var*J_var + 1e-5) ), 9x9 zero-padded box sums.
// cross = IJ - I*J/81 ; I_var = I2 - I^2/81 ; J_var = J2 - J^2/81.
//
// R10 structure (bench 30.8us) + f32x2-packed vertical update:
//   grid (22 strips x 32 images) = 704 blocks, TPB=128, 4 cols/thread,
//   lb(128,5). Interior strips guard-free (peeled warm-up + steady loop);
//   edge strips guarded. Double-buffered smem V exchange, 9-tap horizontal
//   window per emitted row.
//   NEW: vertical running sums kept as packed f32x2 (column pairs).
//   Update uses s=an-ap, u=an+ap:  vI+=s, vI2=fma2(s,u,vI2), and
//   an*bn-ap*bp = 0.5*(u*sd + s*ud)  -> 22 packed ops vs 40 scalar.
//   Block partial -> double atomic; last block finalizes + resets.

#define BW   512
#define BH   512
#define NB   32
#define ROWS 24
#define TPB  128
#define STRIPS 22                    // 21 full strips of 24 + one of 8
#define NBLOCKS (STRIPS * NB)        // 704

typedef unsigned long long u64;

__device__ double       g_acc;   // zero-init at load; reset by last block
__device__ unsigned int g_cnt;

// f32x2 packed ops (Blackwell FFMA2 path — only reachable via PTX).
#define F2ADD(D, A, B) asm("add.rn.f32x2 %0, %1, %2;" : "=l"(D) : "l"(A), "l"(B))
#define F2MUL(D, A, B) asm("mul.rn.f32x2 %0, %1, %2;" : "=l"(D) : "l"(A), "l"(B))
#define F2FMA(D, A, B, C) \
    asm("fma.rn.f32x2 %0, %1, %2, %3;" : "=l"(D) : "l"(A), "l"(B), "l"(C))
#define F2UNPK(LO, HI, V) \
    asm("mov.b64 {%0, %1}, %2;" : "=f"(LO), "=f"(HI) : "l"(V))

__global__ __launch_bounds__(TPB, 5) void ncc_main_k(const float* __restrict__ gI,
                                                     const float* __restrict__ gJ,
                                                     float* __restrict__ out) {
    __shared__ float4 sV[2][5][TPB];     // double-buffered V exchange: 20480 B
    __shared__ float  wsum[TPB / 32];

    const int t    = threadIdx.x;
    const int lane = t & 31;
    const int r0   = blockIdx.x * ROWS;
    const size_t img = (size_t)blockIdx.y * ((size_t)BH * BW);
    const float4 z = make_float4(0.f, 0.f, 0.f, 0.f);
    const float inv81 = 1.0f / 81.0f;
    const u64 NEG1C = 0xBF800000BF800000ULL;   // (-1.f, -1.f)
    const u64 HALFC = 0x3F0000003F000000ULL;   // (0.5f, 0.5f)

    const float4* bI = (const float4*)(gI + img) + t;   // stride BW/4 per row
    const float4* bJ = (const float4*)(gJ + img) + t;

    // Packed V state: index p = column pair (cols 2p, 2p+1).
    u64 vIc[2]  = {0ull, 0ull};
    u64 vJc[2]  = {0ull, 0ull};
    u64 vI2c[2] = {0ull, 0ull};
    u64 vJ2c[2] = {0ull, 0ull};
    u64 vIJc[2] = {0ull, 0ull};
    float acc = 0.f;

// Packed vertical update for one column pair P from packed new/old values.
#define VUPP(P, AN, BN, AO, BO)                                                \
    {                                                                          \
        u64 s_, u_, sd_, ud_, tt_;                                             \
        F2FMA(s_,  (AO), NEG1C, (AN));       /* an - ap */                     \
        F2ADD(u_,  (AN), (AO));              /* an + ap */                     \
        F2FMA(sd_, (BO), NEG1C, (BN));       /* bn - bp */                     \
        F2ADD(ud_, (BN), (BO));              /* bn + bp */                     \
        F2ADD(vIc[P],  vIc[P],  s_);                                           \
        F2ADD(vJc[P],  vJc[P],  sd_);                                          \
        F2FMA(vI2c[P], s_,  u_,  vI2c[P]);                                     \
        F2FMA(vJ2c[P], sd_, ud_, vJ2c[P]);                                     \
        F2MUL(tt_, u_, sd_);                                                   \
        F2FMA(tt_, s_, ud_, tt_);                                              \
        F2FMA(vIJc[P], tt_, HALFC, vIJc[P]);                                   \
    }

// Full vertical update from float4 new/old rows (reinterpreted as u64 pairs).
#define VUPDATE(A1, B1, AO, BO)                                                \
    {                                                                          \
        const u64* anp = (const u64*)&(A1);                                    \
        const u64* bnp = (const u64*)&(B1);                                    \
        const u64* aop = (const u64*)&(AO);                                    \
        const u64* bop = (const u64*)&(BO);                                    \
        VUPP(0, anp[0], bnp[0], aop[0], bop[0])                                \
        VUPP(1, anp[1], bnp[1], aop[1], bop[1])                                \
    }

#define DO_WIN(P, W0, W1, W2, W3)                                              \
    {                                                                          \
        float4 L = (t > 0)       ? sV[buf][P][t - 1] : z;                      \
        float4 R = (t < TPB - 1) ? sV[buf][P][t + 1] : z;                      \
        float v0 = L.x, v1 = L.y, v2 = L.z, v3 = L.w;                          \
        float v4 = (W0), v5 = (W1), v6 = (W2), v7 = (W3);                      \
        float v8 = R.x, v9 = R.y, v10 = R.z, v11 = R.w;                        \
        float w = ((v0 + v1) + (v2 + v3)) + ((v4 + v5) + (v6 + v7)) + v8;      \
        box[P][0] = w;                                                         \
        box[P][1] = w = w - v0 + v9;                                           \
        box[P][2] = w = w - v1 + v10;                                          \
        box[P][3] =     w - v2 + v11;                                          \
    }

// Emit one output row via smem exchange buffer BUF (0/1).
#define EMIT(BUF)                                                              \
    {                                                                          \
        const int buf = (BUF);                                                 \
        ((ulonglong2*)&sV[buf][0][t])->x = vIc[0];                             \
        ((ulonglong2*)&sV[buf][0][t])->y = vIc[1];                             \
        ((ulonglong2*)&sV[buf][1][t])->x = vJc[0];                             \
        ((ulonglong2*)&sV[buf][1][t])->y = vJc[1];                             \
        ((ulonglong2*)&sV[buf][2][t])->x = vI2c[0];                            \
        ((ulonglong2*)&sV[buf][2][t])->y = vI2c[1];                            \
        ((ulonglong2*)&sV[buf][3][t])->x = vJ2c[0];                            \
        ((ulonglong2*)&sV[buf][3][t])->y = vJ2c[1];                            \
        ((ulonglong2*)&sV[buf][4][t])->x = vIJc[0];                            \
        ((ulonglong2*)&sV[buf][4][t])->y = vIJc[1];                            \
        __syncthreads();                                                       \
        float o0, o1, o2, o3;                                                  \
        float box[5][4];                                                       \
        F2UNPK(o0, o1, vIc[0]);  F2UNPK(o2, o3, vIc[1]);                       \
        DO_WIN(0, o0, o1, o2, o3)                                              \
        F2UNPK(o0, o1, vJc[0]);  F2UNPK(o2, o3, vJc[1]);                       \
        DO_WIN(1, o0, o1, o2, o3)                                              \
        F2UNPK(o0, o1, vI2c[0]); F2UNPK(o2, o3, vI2c[1]);                      \
        DO_WIN(2, o0, o1, o2, o3)                                              \
        F2UNPK(o0, o1, vJ2c[0]); F2UNPK(o2, o3, vJ2c[1]);                      \
        DO_WIN(3, o0, o1, o2, o3)                                              \
        F2UNPK(o0, o1, vIJc[0]); F2UNPK(o2, o3, vIJc[1]);                      \
        DO_WIN(4, o0, o1, o2, o3)                                              \
        _Pragma("unroll")                                                      \
        for (int c = 0; c < 4; ++c) {                                          \
            float sI = box[0][c], sJ = box[1][c];                              \
            float cross = fmaf(sI * sJ, -inv81, box[4][c]);                    \
            float Iv    = fmaf(sI * sI, -inv81, box[2][c]);                    \
            float Jv    = fmaf(sJ * sJ, -inv81, box[3][c]);                    \
            float den   = fmaf(Iv, Jv, 1e-5f);                                 \
            acc += __fdividef(cross * cross, den);                             \
        }                                                                      \
    }

    if (r0 >= ROWS && r0 + ROWS + 4 <= BH) {
        // ---------- interior strip (20 of 22): zero range checks ----------
#pragma unroll
        for (int it = 0; it < 8; ++it) {
            const int rn = r0 - 4 + it;
            float4 a1 = __ldg(bI + (size_t)rn * (BW / 4));
            float4 b1 = __ldg(bJ + (size_t)rn * (BW / 4));
            float4 zo = z;
            VUPDATE(a1, b1, zo, zo)
        }
        {   // it = 8: window full, first emit, still no subtract.
            float4 a1 = __ldg(bI + (size_t)(r0 + 4) * (BW / 4));
            float4 b1 = __ldg(bJ + (size_t)(r0 + 4) * (BW / 4));
            float4 zo = z;
            VUPDATE(a1, b1, zo, zo)
            EMIT(0)
        }
#pragma unroll 2
        for (int it = 9; it < ROWS + 8; ++it) {
            const int rn = r0 - 4 + it;
            const int ro = rn - 9;
            float4 a1 = __ldg(bI + (size_t)rn * (BW / 4));
            float4 b1 = __ldg(bJ + (size_t)rn * (BW / 4));
            float4 ao = __ldg(bI + (size_t)ro * (BW / 4));
            float4 bo = __ldg(bJ + (size_t)ro * (BW / 4));
            VUPDATE(a1, b1, ao, bo)
            EMIT(it & 1)
        }
    } else {
        // ---------- edge strips: guarded generic loop ----------
        const int rows_eff = min(ROWS, BH - r0);
        const int iters = rows_eff + 8;
#pragma unroll 2
        for (int it = 0; it < iters; ++it) {
            const int rn = r0 - 4 + it;
            const int ro = rn - 9;
            float4 a1 = z, b1 = z, ao = z, bo = z;
            if (rn >= 0 && rn < BH) {
                a1 = __ldg(bI + (size_t)rn * (BW / 4));
                b1 = __ldg(bJ + (size_t)rn * (BW / 4));
            }
            if (it >= 9 && ro >= 0) {   // only rows actually added earlier
                ao = __ldg(bI + (size_t)ro * (BW / 4));
                bo = __ldg(bJ + (size_t)ro * (BW / 4));
            }
            VUPDATE(a1, b1, ao, bo)
            if (it >= 8) EMIT(it & 1)
        }
    }
#undef DO_WIN
#undef EMIT
#undef VUPDATE
#undef VUPP

    // Block reduction -> global double atomic; last block finalizes + resets.
#pragma unroll
    for (int o = 16; o; o >>= 1) acc += __shfl_xor_sync(0xffffffffu, acc, o);
    if (lane == 0) wsum[t >> 5] = acc;
    __syncthreads();
    if (t == 0) {
        float bs = 0.f;
#pragma unroll
        for (int w = 0; w < TPB / 32; ++w) bs += wsum[w];
        atomicAdd(&g_acc, (double)bs);
        __threadfence();
        unsigned int done = atomicAdd(&g_cnt, 1u);
        if (done == NBLOCKS - 1) {
            __threadfence();
            double v = *((volatile double*)&g_acc);
            out[0] = (float)(-v * (1.0 / (double)((long long)NB * BH * BW)));
            g_acc = 0.0;          // reset for next graph replay
            g_cnt = 0u;
        }
    }
}

extern "C" void kernel_launch(void* const* d_in, const int* in_sizes, int n_in,
                              void* d_out, int out_size) {
    const float* I = (const float*)d_in[0];
    const float* J = (const float*)d_in[1];
    float* out = (float*)d_out;

    dim3 grid(STRIPS, NB);   // (22, 32) = 704 blocks, single wave at 5/SM
    ncc_main_k<<<grid, TPB>>>(I, J, out);
}